// round 1
// baseline (speedup 1.0000x reference)
#include <cuda_runtime.h>
#include <cuda_bf16.h>
#include <math.h>

#define TT 512
#define NN 1024
#define DD 256
#define M_ROWS (TT * NN)   // 524288 rows of the fused (t,n) dimension

// Scratch for scores e[t,n] (2 MB) — __device__ global per allocation rules.
__device__ float g_e[M_ROWS];

// ---------------------------------------------------------------------------
// Kernel A: fused GEMM + tanh + score reduction.
//   z[row][e] = sum_k H[row][k] * fc_w[e][k] + fc_b[e]
//   g_e[row]  = sum_e tanh(z[row][e]) * score_w[e]
// Tiling: BM=64 rows x full 256 e-columns per block, BK=16 K-chunks.
// 256 threads, each owns an 8x8 micro-tile (row_t = tid>>5, col_t = tid&31).
// ---------------------------------------------------------------------------
#define BM 64
#define BK 16

__global__ __launch_bounds__(256, 2)
void gemm_score_kernel(const float* __restrict__ H,
                       const float* __restrict__ W,
                       const float* __restrict__ bias,
                       const float* __restrict__ swt)
{
    __shared__ float As[BK][BM];   // [k][row]
    __shared__ float Bs[BK][DD];   // [k][e]

    const int tid   = threadIdx.x;
    const int row0  = blockIdx.x * BM;
    const int col_t = tid & 31;    // 0..31 -> e-group of 8
    const int row_t = tid >> 5;    // 0..7  -> row-group of 8 (one warp per group)

    float acc[8][8];
    #pragma unroll
    for (int i = 0; i < 8; i++)
        #pragma unroll
        for (int j = 0; j < 8; j++) acc[i][j] = 0.0f;

    for (int k0 = 0; k0 < DD; k0 += BK) {
        // --- load A tile: 64 rows x 16 k (one float4 per thread) ---
        {
            int r  = tid >> 2;          // 0..63
            int kq = (tid & 3) * 4;     // 0,4,8,12
            float4 v = *reinterpret_cast<const float4*>(
                &H[(size_t)(row0 + r) * DD + k0 + kq]);
            As[kq + 0][r] = v.x; As[kq + 1][r] = v.y;
            As[kq + 2][r] = v.z; As[kq + 3][r] = v.w;
        }
        // --- load B tile: 256 e x 16 k (4 float4 passes per thread) ---
        #pragma unroll
        for (int p = 0; p < 4; p++) {
            int e  = (tid >> 2) + p * 64;
            int kq = (tid & 3) * 4;
            float4 v = *reinterpret_cast<const float4*>(
                &W[(size_t)e * DD + k0 + kq]);
            Bs[kq + 0][e] = v.x; Bs[kq + 1][e] = v.y;
            Bs[kq + 2][e] = v.z; Bs[kq + 3][e] = v.w;
        }
        __syncthreads();

        #pragma unroll
        for (int kk = 0; kk < BK; kk++) {
            float a[8], b[8];
            *reinterpret_cast<float4*>(&a[0]) =
                *reinterpret_cast<const float4*>(&As[kk][row_t * 8]);
            *reinterpret_cast<float4*>(&a[4]) =
                *reinterpret_cast<const float4*>(&As[kk][row_t * 8 + 4]);
            *reinterpret_cast<float4*>(&b[0]) =
                *reinterpret_cast<const float4*>(&Bs[kk][col_t * 8]);
            *reinterpret_cast<float4*>(&b[4]) =
                *reinterpret_cast<const float4*>(&Bs[kk][col_t * 8 + 4]);
            #pragma unroll
            for (int i = 0; i < 8; i++)
                #pragma unroll
                for (int j = 0; j < 8; j++)
                    acc[i][j] = fmaf(a[i], b[j], acc[i][j]);
        }
        __syncthreads();
    }

    // --- epilogue: tanh + score-weighted reduce over e ---
    float bb[8], ss[8];
    *reinterpret_cast<float4*>(&bb[0]) =
        *reinterpret_cast<const float4*>(&bias[col_t * 8]);
    *reinterpret_cast<float4*>(&bb[4]) =
        *reinterpret_cast<const float4*>(&bias[col_t * 8 + 4]);
    *reinterpret_cast<float4*>(&ss[0]) =
        *reinterpret_cast<const float4*>(&swt[col_t * 8]);
    *reinterpret_cast<float4*>(&ss[4]) =
        *reinterpret_cast<const float4*>(&swt[col_t * 8 + 4]);

    #pragma unroll
    for (int i = 0; i < 8; i++) {
        float partial = 0.0f;
        #pragma unroll
        for (int j = 0; j < 8; j++)
            partial += tanhf(acc[i][j] + bb[j]) * ss[j];
        // all 32 lanes of this warp share the same 8 rows -> warp reduce
        #pragma unroll
        for (int off = 16; off; off >>= 1)
            partial += __shfl_xor_sync(0xffffffffu, partial, off);
        if (col_t == 0)
            g_e[row0 + row_t * 8 + i] = partial;
    }
}

// ---------------------------------------------------------------------------
// Kernel B: causal softmax-weighted prefix average.
// One block per n (1024 blocks), 256 threads = one d each.
// Global-max reformulation: w_t = exp(e_t - M), S_t = prefix-sum(w),
// C[t,n,d] = (sum_{s<=t} w_s * H[s,n,d]) / S_t   -> 1 FMA + 1 MUL / element.
// ---------------------------------------------------------------------------
__global__ __launch_bounds__(256)
void attend_kernel(const float* __restrict__ H, float* __restrict__ C)
{
    __shared__ float se[TT];
    __shared__ float sw[TT];    // exp(e_t - M)
    __shared__ float sinv[TT];  // 1 / S_t

    const int n   = blockIdx.x;
    const int tid = threadIdx.x;

    // gather scores for this n
    for (int t = tid; t < TT; t += 256)
        se[t] = g_e[t * NN + n];
    __syncthreads();

    // serial max + prefix scan on thread 0 (512 cheap iterations,
    // overlapped across the ~7 concurrent blocks per SM)
    if (tid == 0) {
        float m = -INFINITY;
        #pragma unroll 8
        for (int t = 0; t < TT; t++) m = fmaxf(m, se[t]);
        float s = 0.0f;
        for (int t = 0; t < TT; t++) {
            float w = __expf(se[t] - m);
            s += w;
            sw[t]   = w;
            sinv[t] = __fdividef(1.0f, s);
        }
    }
    __syncthreads();

    const size_t stride = (size_t)NN * DD;
    const float* hp = H + (size_t)n * DD + tid;
    float*       cp = C + (size_t)n * DD + tid;

    float num = 0.0f;
    #pragma unroll 4
    for (int t = 0; t < TT; t++) {
        float h = hp[(size_t)t * stride];
        num = fmaf(sw[t], h, num);
        cp[(size_t)t * stride] = num * sinv[t];
    }
}

// ---------------------------------------------------------------------------
extern "C" void kernel_launch(void* const* d_in, const int* in_sizes, int n_in,
                              void* d_out, int out_size)
{
    const float* H  = (const float*)d_in[0];  // (T,N,D)
    const float* W  = (const float*)d_in[1];  // (D,D) fc_w[e][d]
    const float* b  = (const float*)d_in[2];  // (D,)
    const float* sv = (const float*)d_in[3];  // (D,)
    float* C = (float*)d_out;                 // (T,N,D)

    gemm_score_kernel<<<M_ROWS / BM, 256>>>(H, W, b, sv);
    attend_kernel<<<NN, 256>>>(H, C);
}

// round 3
// speedup vs baseline: 1.7727x; 1.7727x over previous
#include <cuda_runtime.h>
#include <cuda_fp16.h>
#include <math.h>
#include <stdint.h>

#define TT 512
#define NN 1024
#define DD 256
#define M_ROWS (TT * NN)

__device__ float g_e[M_ROWS];
__device__ __align__(16) __half g_Whi[DD * DD];
__device__ __align__(16) __half g_Wlo[DD * DD];

// ---------------------------------------------------------------------------
// SMEM layout (bytes, dynamic). Rows padded to 80B (32 halves data + 16B pad)
// for conflict-free ldmatrix (bank base 20r % 32 distinct over 8 rows).
// ---------------------------------------------------------------------------
#define SA_HI   0                   // 128 rows * 80
#define SA_LO   10240
#define SB0     20480               // + buf*40960 + split*20480 (256 rows * 80)
#define SBIAS   102400
#define SSW     103424
#define SRED    104448
#define SMTOT   104960

// ---------------------------------------------------------------------------
// PTX helpers (baseline ISA only -- no tcgen05!)
// ---------------------------------------------------------------------------
__device__ __forceinline__ uint32_t smem_u32(const void* p) {
    uint32_t a;
    asm("{ .reg .u64 t; cvta.to.shared.u64 t, %1; cvt.u32.u64 %0, t; }"
        : "=r"(a) : "l"(p));
    return a;
}
__device__ __forceinline__ void cp_async16(uint32_t dst, const void* src) {
    asm volatile("cp.async.cg.shared.global [%0], [%1], 16;"
                 :: "r"(dst), "l"(src) : "memory");
}
#define CP_COMMIT() asm volatile("cp.async.commit_group;" ::: "memory")
#define CP_WAIT(n)  asm volatile("cp.async.wait_group %0;" :: "n"(n) : "memory")

__device__ __forceinline__ void ldsm4(uint32_t* r, uint32_t addr) {
    asm volatile("ldmatrix.sync.aligned.m8n8.x4.shared.b16 {%0,%1,%2,%3}, [%4];"
                 : "=r"(r[0]), "=r"(r[1]), "=r"(r[2]), "=r"(r[3]) : "r"(addr));
}
__device__ __forceinline__ void mma16816(float* c, const uint32_t* a,
                                         uint32_t b0, uint32_t b1) {
    asm volatile(
        "mma.sync.aligned.m16n8k16.row.col.f32.f16.f16.f32 "
        "{%0,%1,%2,%3}, {%4,%5,%6,%7}, {%8,%9}, {%0,%1,%2,%3};"
        : "+f"(c[0]), "+f"(c[1]), "+f"(c[2]), "+f"(c[3])
        : "r"(a[0]), "r"(a[1]), "r"(a[2]), "r"(a[3]), "r"(b0), "r"(b1));
}

// fp32 -> fp16 hi/lo split of 8 consecutive floats
__device__ __forceinline__ void cvt8h(const float4& u, const float4& v,
                                      uint4& hi, uint4& lo) {
    __half2 h0 = __floats2half2_rn(u.x, u.y);
    __half2 h1 = __floats2half2_rn(u.z, u.w);
    __half2 h2 = __floats2half2_rn(v.x, v.y);
    __half2 h3 = __floats2half2_rn(v.z, v.w);
    float2 f0 = __half22float2(h0), f1 = __half22float2(h1);
    float2 f2 = __half22float2(h2), f3 = __half22float2(h3);
    __half2 l0 = __floats2half2_rn(u.x - f0.x, u.y - f0.y);
    __half2 l1 = __floats2half2_rn(u.z - f1.x, u.w - f1.y);
    __half2 l2 = __floats2half2_rn(v.x - f2.x, v.y - f2.y);
    __half2 l3 = __floats2half2_rn(v.z - f3.x, v.w - f3.y);
    hi.x = *(uint32_t*)&h0; hi.y = *(uint32_t*)&h1;
    hi.z = *(uint32_t*)&h2; hi.w = *(uint32_t*)&h3;
    lo.x = *(uint32_t*)&l0; lo.y = *(uint32_t*)&l1;
    lo.z = *(uint32_t*)&l2; lo.w = *(uint32_t*)&l3;
}

// MUFU-free tanh: FMA/ALU only (~22 ops), abs err ~2e-5.
__device__ __forceinline__ float tanh_fast(float x) {
    float ax = fminf(fabsf(x), 15.0f);
    float u  = ax * 2.8853900817779268f;           // 2*log2(e)*|x|
    float t  = u + 12582912.0f;                    // round-to-int trick
    float kf = t - 12582912.0f;
    float r  = u - kf;                             // [-0.5, 0.5]
    float p  = 0.009618130f;                       // 2^r Taylor deg-4
    p = fmaf(p, r, 0.055504109f);
    p = fmaf(p, r, 0.240226507f);
    p = fmaf(p, r, 0.693147181f);
    p = fmaf(p, r, 1.0f);
    int ki  = __float_as_int(t) - 0x4B400000;      // integer k (k >= 0)
    float E = __int_as_float(__float_as_int(p) + (ki << 23));  // e^{2|x|}
    float y = E + 1.0f;
    float rc = __int_as_float(0x7EF311C3 - __float_as_int(y)); // ~1/y est
    rc = rc * fmaf(-y, rc, 2.0f);                  // 3 Newton steps
    rc = rc * fmaf(-y, rc, 2.0f);
    rc = rc * fmaf(-y, rc, 2.0f);
    float th = fmaf(-2.0f, rc, 1.0f);              // tanh(|x|)
    return __int_as_float(__float_as_int(th) |
                          (__float_as_int(x) & 0x80000000));
}

// ---------------------------------------------------------------------------
// Prep: split W (256x256 fp32, [e][k]) into fp16 hi/lo once.
// ---------------------------------------------------------------------------
__global__ void w_prep(const float* __restrict__ W) {
    int i = blockIdx.x * blockDim.x + threadIdx.x;      // 8192 threads * 8 elems
    const float4* p = reinterpret_cast<const float4*>(W) + i * 2;
    float4 u = p[0], v = p[1];
    uint4 hi, lo;
    cvt8h(u, v, hi, lo);
    reinterpret_cast<uint4*>(g_Whi)[i] = hi;
    reinterpret_cast<uint4*>(g_Wlo)[i] = lo;
}

// ---------------------------------------------------------------------------
// Kernel A: HMMA GEMM (fp16 split x3) + FMA-tanh + score reduce -> g_e
// grid = 4096 (M/128), 512 threads (16 warps, 4 row x 4 col).
// ---------------------------------------------------------------------------
__global__ __launch_bounds__(512, 1)
void gemm_score_hmma(const float* __restrict__ H,
                     const float* __restrict__ bias,
                     const float* __restrict__ swt)
{
    extern __shared__ char smem[];
    const uint32_t sb = smem_u32(smem);
    const int tid  = threadIdx.x;
    const int lane = tid & 31;
    const int warp = tid >> 5;
    const int wr   = warp >> 2;       // 0..3: rows 32*wr
    const int wc   = warp & 3;        // 0..3: cols 64*wc
    const int row0 = blockIdx.x * 128;

    if (tid < 256) {
        ((float*)(smem + SBIAS))[tid] = bias[tid];
        ((float*)(smem + SSW))[tid]   = swt[tid];
    }
    if (tid < 128) ((float*)(smem + SRED))[tid] = 0.0f;

    // A loader mapping: each thread owns 8 k of one row
    const int arow  = tid >> 2;
    const int akseg = tid & 3;
    const float* aptr = H + (size_t)(row0 + arow) * DD + akseg * 8;
    char* a_hi_sts = smem + SA_HI + arow * 80 + akseg * 16;
    char* a_lo_sts = smem + SA_LO + arow * 80 + akseg * 16;

    float acc[2][8][4];
    #pragma unroll
    for (int m = 0; m < 2; m++)
        #pragma unroll
        for (int n = 0; n < 8; n++)
            #pragma unroll
            for (int e = 0; e < 4; e++) acc[m][n][e] = 0.0f;

    // B cp.async mapping: 4 chunks of 16B per thread per k-chunk
    // idx = tid + p*512: split = idx>>10, row = (idx&1023)>>2, ch = idx&3
    auto cpB = [&](int c, int buf) {
        #pragma unroll
        for (int p = 0; p < 4; p++) {
            int idx   = tid + p * 512;
            int split = idx >> 10;
            int i     = idx & 1023;
            int r     = i >> 2;
            int ch    = i & 3;
            const __half* src = (split ? g_Wlo : g_Whi)
                                + (size_t)r * DD + c * 32 + ch * 8;
            uint32_t dst = sb + SB0 + buf * 40960 + split * 20480
                           + r * 80 + ch * 16;
            cp_async16(dst, src);
        }
        CP_COMMIT();
    };

    // ldmatrix lane addressing (rows lane&15, k-half lane>>4)
    const int lrow = lane & 15;
    const int lkh  = lane >> 4;
    const uint32_t aBase = sb + (wr * 32 + lrow) * 80 + lkh * 16;
    const uint32_t bBase = sb + SB0 + (wc * 64 + lrow) * 80 + lkh * 16;

    // ---- software pipeline prologue ----
    float4 ar0, ar1;
    cpB(0, 0);
    ar0 = *reinterpret_cast<const float4*>(aptr);
    ar1 = *reinterpret_cast<const float4*>(aptr + 4);
    {
        uint4 hi, lo; cvt8h(ar0, ar1, hi, lo);
        *reinterpret_cast<uint4*>(a_hi_sts) = hi;
        *reinterpret_cast<uint4*>(a_lo_sts) = lo;
    }
    cpB(1, 1);
    ar0 = *reinterpret_cast<const float4*>(aptr + 32);
    ar1 = *reinterpret_cast<const float4*>(aptr + 36);
    CP_WAIT(1);
    __syncthreads();

    for (int c = 0; c < 8; c++) {
        const int buf = c & 1;
        // ---- MMA over chunk c: 3 split pairs (HH, H*L, L*H) ----
        #pragma unroll
        for (int pr = 0; pr < 3; pr++) {
            const uint32_t aoff = (pr == 2) ? (uint32_t)SA_LO : 0u;
            const uint32_t boff = buf * 40960u + ((pr == 1) ? 20480u : 0u);
            #pragma unroll
            for (int ks = 0; ks < 2; ks++) {
                uint32_t af[2][4];
                #pragma unroll
                for (int mt = 0; mt < 2; mt++)
                    ldsm4(af[mt], aBase + aoff + mt * (16 * 80) + ks * 32);
                #pragma unroll
                for (int ntp = 0; ntp < 4; ntp++) {
                    uint32_t bf[4];
                    ldsm4(bf, bBase + boff + ntp * (16 * 80) + ks * 32);
                    #pragma unroll
                    for (int mt = 0; mt < 2; mt++) {
                        mma16816(acc[mt][ntp * 2 + 0], af[mt], bf[0], bf[2]);
                        mma16816(acc[mt][ntp * 2 + 1], af[mt], bf[1], bf[3]);
                    }
                }
            }
        }
        __syncthreads();
        if (c < 7) {
            uint4 hi, lo; cvt8h(ar0, ar1, hi, lo);
            *reinterpret_cast<uint4*>(a_hi_sts) = hi;
            *reinterpret_cast<uint4*>(a_lo_sts) = lo;
            if (c < 6) {
                cpB(c + 2, buf);
                ar0 = *reinterpret_cast<const float4*>(aptr + (c + 2) * 32);
                ar1 = *reinterpret_cast<const float4*>(aptr + (c + 2) * 32 + 4);
                CP_WAIT(1);
            } else {
                CP_WAIT(0);
            }
            __syncthreads();
        }
    }

    // ---- epilogue: tanh + score-weighted reduce over the 256 e-columns ----
    const float* sbias = (const float*)(smem + SBIAS);
    const float* ssw   = (const float*)(smem + SSW);
    float* sred        = (float*)(smem + SRED);

    #pragma unroll
    for (int mt = 0; mt < 2; mt++) {
        #pragma unroll
        for (int h = 0; h < 2; h++) {
            float part = 0.0f;
            const int lrow_out = wr * 32 + mt * 16 + (lane >> 2) + h * 8;
            #pragma unroll
            for (int nt = 0; nt < 8; nt++) {
                const int col = wc * 64 + nt * 8 + (lane & 3) * 2;
                float2 bb = *reinterpret_cast<const float2*>(&sbias[col]);
                float2 ws = *reinterpret_cast<const float2*>(&ssw[col]);
                part = fmaf(tanh_fast(acc[mt][nt][h * 2 + 0] + bb.x), ws.x, part);
                part = fmaf(tanh_fast(acc[mt][nt][h * 2 + 1] + bb.y), ws.y, part);
            }
            part += __shfl_xor_sync(0xffffffffu, part, 1);
            part += __shfl_xor_sync(0xffffffffu, part, 2);
            if ((lane & 3) == 0) atomicAdd(&sred[lrow_out], part);
        }
    }
    __syncthreads();
    if (tid < 128) g_e[row0 + tid] = sred[tid];
}

// ---------------------------------------------------------------------------
// Kernel B: causal softmax-weighted prefix average (unchanged, near DRAM roof)
// ---------------------------------------------------------------------------
__global__ __launch_bounds__(256)
void attend_kernel(const float* __restrict__ H, float* __restrict__ C)
{
    __shared__ float se[TT];
    __shared__ float sw[TT];
    __shared__ float sinv[TT];

    const int n   = blockIdx.x;
    const int tid = threadIdx.x;

    for (int t = tid; t < TT; t += 256)
        se[t] = g_e[t * NN + n];
    __syncthreads();

    if (tid == 0) {
        float m = -INFINITY;
        #pragma unroll 8
        for (int t = 0; t < TT; t++) m = fmaxf(m, se[t]);
        float s = 0.0f;
        for (int t = 0; t < TT; t++) {
            float w = __expf(se[t] - m);
            s += w;
            sw[t]   = w;
            sinv[t] = __fdividef(1.0f, s);
        }
    }
    __syncthreads();

    const size_t stride = (size_t)NN * DD;
    const float* hp = H + (size_t)n * DD + tid;
    float*       cp = C + (size_t)n * DD + tid;

    float num = 0.0f;
    #pragma unroll 4
    for (int t = 0; t < TT; t++) {
        float h = hp[(size_t)t * stride];
        num = fmaf(sw[t], h, num);
        cp[(size_t)t * stride] = num * sinv[t];
    }
}

// ---------------------------------------------------------------------------
extern "C" void kernel_launch(void* const* d_in, const int* in_sizes, int n_in,
                              void* d_out, int out_size)
{
    const float* H  = (const float*)d_in[0];
    const float* W  = (const float*)d_in[1];
    const float* b  = (const float*)d_in[2];
    const float* sv = (const float*)d_in[3];
    float* C = (float*)d_out;

    cudaFuncSetAttribute(gemm_score_hmma,
                         cudaFuncAttributeMaxDynamicSharedMemorySize, SMTOT);

    w_prep<<<16, 512>>>(W);
    gemm_score_hmma<<<M_ROWS / 128, 512, SMTOT>>>(H, b, sv);
    attend_kernel<<<NN, 256>>>(H, C);
}

// round 4
// speedup vs baseline: 1.7805x; 1.0044x over previous
#include <cuda_runtime.h>
#include <cuda_fp16.h>
#include <math.h>
#include <stdint.h>

#define TT 512
#define NN 1024
#define DD 256
#define M_ROWS (TT * NN)

__device__ float g_e[M_ROWS];
__device__ __align__(16) __half g_Whi[DD * DD];

// ---------------------------------------------------------------------------
// SMEM layout (bytes, dynamic). Rows padded to 80B (32 halves + 16B pad):
// conflict-free ldmatrix (20r mod 32 distinct over 8-row phases).
//   A: buf0 hi 0, buf0 lo 10240, buf1 hi 20480, buf1 lo 30720   (128 rows*80)
//   B: 40960 + buf*20480                                        (256 rows*80)
// ---------------------------------------------------------------------------
#define SA(buf)    ((buf) * 20480)
#define SA_LO_OFF  10240
#define SB(buf)    (40960 + (buf) * 20480)
#define SBIAS      81920
#define SSW        82944
#define SRED       83968
#define SMTOT      84480

// ---------------------------------------------------------------------------
// PTX helpers (baseline ISA only -- no tcgen05 on this toolchain!)
// ---------------------------------------------------------------------------
__device__ __forceinline__ uint32_t smem_u32(const void* p) {
    uint32_t a;
    asm("{ .reg .u64 t; cvta.to.shared.u64 t, %1; cvt.u32.u64 %0, t; }"
        : "=r"(a) : "l"(p));
    return a;
}
__device__ __forceinline__ void cp_async16(uint32_t dst, const void* src) {
    asm volatile("cp.async.cg.shared.global [%0], [%1], 16;"
                 :: "r"(dst), "l"(src) : "memory");
}
#define CP_COMMIT() asm volatile("cp.async.commit_group;" ::: "memory")
#define CP_WAIT(n)  asm volatile("cp.async.wait_group %0;" :: "n"(n) : "memory")

__device__ __forceinline__ void ldsm4(uint32_t* r, uint32_t addr) {
    asm volatile("ldmatrix.sync.aligned.m8n8.x4.shared.b16 {%0,%1,%2,%3}, [%4];"
                 : "=r"(r[0]), "=r"(r[1]), "=r"(r[2]), "=r"(r[3]) : "r"(addr));
}
__device__ __forceinline__ void mma16816(float* c, const uint32_t* a,
                                         uint32_t b0, uint32_t b1) {
    asm volatile(
        "mma.sync.aligned.m16n8k16.row.col.f32.f16.f16.f32 "
        "{%0,%1,%2,%3}, {%4,%5,%6,%7}, {%8,%9}, {%0,%1,%2,%3};"
        : "+f"(c[0]), "+f"(c[1]), "+f"(c[2]), "+f"(c[3])
        : "r"(a[0]), "r"(a[1]), "r"(a[2]), "r"(a[3]), "r"(b0), "r"(b1));
}

// fp32 -> fp16 hi/lo split of 8 consecutive floats
__device__ __forceinline__ void cvt8h(const float4& u, const float4& v,
                                      uint4& hi, uint4& lo) {
    __half2 h0 = __floats2half2_rn(u.x, u.y);
    __half2 h1 = __floats2half2_rn(u.z, u.w);
    __half2 h2 = __floats2half2_rn(v.x, v.y);
    __half2 h3 = __floats2half2_rn(v.z, v.w);
    float2 f0 = __half22float2(h0), f1 = __half22float2(h1);
    float2 f2 = __half22float2(h2), f3 = __half22float2(h3);
    __half2 l0 = __floats2half2_rn(u.x - f0.x, u.y - f0.y);
    __half2 l1 = __floats2half2_rn(u.z - f1.x, u.w - f1.y);
    __half2 l2 = __floats2half2_rn(v.x - f2.x, v.y - f2.y);
    __half2 l3 = __floats2half2_rn(v.z - f3.x, v.w - f3.y);
    hi.x = *(uint32_t*)&h0; hi.y = *(uint32_t*)&h1;
    hi.z = *(uint32_t*)&h2; hi.w = *(uint32_t*)&h3;
    lo.x = *(uint32_t*)&l0; lo.y = *(uint32_t*)&l1;
    lo.z = *(uint32_t*)&l2; lo.w = *(uint32_t*)&l3;
}

// MUFU-free tanh: FMA/ALU only (~22 ops), abs err ~2e-5.
__device__ __forceinline__ float tanh_fast(float x) {
    float ax = fminf(fabsf(x), 15.0f);
    float u  = ax * 2.8853900817779268f;           // 2*log2(e)*|x|
    float t  = u + 12582912.0f;                    // round-to-int trick
    float kf = t - 12582912.0f;
    float r  = u - kf;                             // [-0.5, 0.5]
    float p  = 0.009618130f;                       // 2^r Taylor deg-4
    p = fmaf(p, r, 0.055504109f);
    p = fmaf(p, r, 0.240226507f);
    p = fmaf(p, r, 0.693147181f);
    p = fmaf(p, r, 1.0f);
    int ki  = __float_as_int(t) - 0x4B400000;      // integer k (k >= 0)
    float E = __int_as_float(__float_as_int(p) + (ki << 23));  // e^{2|x|}
    float y = E + 1.0f;
    float rc = __int_as_float(0x7EF311C3 - __float_as_int(y)); // ~1/y est
    rc = rc * fmaf(-y, rc, 2.0f);                  // 3 Newton steps
    rc = rc * fmaf(-y, rc, 2.0f);
    rc = rc * fmaf(-y, rc, 2.0f);
    float th = fmaf(-2.0f, rc, 1.0f);              // tanh(|x|)
    return __int_as_float(__float_as_int(th) |
                          (__float_as_int(x) & 0x80000000));
}

// ---------------------------------------------------------------------------
// Prep: W (256x256 fp32, [e][k]) -> fp16 hi once.
// ---------------------------------------------------------------------------
__global__ void w_prep(const float* __restrict__ W) {
    int i = blockIdx.x * blockDim.x + threadIdx.x;      // 8192 thr * 8 elems
    const float4* p = reinterpret_cast<const float4*>(W) + i * 2;
    float4 u = p[0], v = p[1];
    __half2 h0 = __floats2half2_rn(u.x, u.y);
    __half2 h1 = __floats2half2_rn(u.z, u.w);
    __half2 h2 = __floats2half2_rn(v.x, v.y);
    __half2 h3 = __floats2half2_rn(v.z, v.w);
    uint4 hi;
    hi.x = *(uint32_t*)&h0; hi.y = *(uint32_t*)&h1;
    hi.z = *(uint32_t*)&h2; hi.w = *(uint32_t*)&h3;
    reinterpret_cast<uint4*>(g_Whi)[i] = hi;
}

// ---------------------------------------------------------------------------
// Kernel A: HMMA GEMM, 2-product split (Ahi*B + Alo*B), full double-buffer,
// one __syncthreads per k-chunk. grid = 4096 (M/128), 512 threads.
// ---------------------------------------------------------------------------
__global__ __launch_bounds__(512, 1)
void gemm_score_hmma(const float* __restrict__ H,
                     const float* __restrict__ bias,
                     const float* __restrict__ swt)
{
    extern __shared__ char smem[];
    const uint32_t sb = smem_u32(smem);
    const int tid  = threadIdx.x;
    const int lane = tid & 31;
    const int warp = tid >> 5;
    const int wr   = warp >> 2;       // 0..3: rows 32*wr
    const int wc   = warp & 3;        // 0..3: cols 64*wc
    const int row0 = blockIdx.x * 128;

    if (tid < 256) {
        ((float*)(smem + SBIAS))[tid] = bias[tid];
        ((float*)(smem + SSW))[tid]   = swt[tid];
    }
    if (tid < 128) ((float*)(smem + SRED))[tid] = 0.0f;

    // A loader mapping: each thread owns 8 k of one row
    const int arow  = tid >> 2;
    const int akseg = tid & 3;
    const float* aptr = H + (size_t)(row0 + arow) * DD + akseg * 8;
    const uint32_t a_sts = (uint32_t)(arow * 80 + akseg * 16);

    float acc[2][8][4];
    #pragma unroll
    for (int m = 0; m < 2; m++)
        #pragma unroll
        for (int n = 0; n < 8; n++)
            #pragma unroll
            for (int e = 0; e < 4; e++) acc[m][n][e] = 0.0f;

    // B cp.async: 1024 x 16B per chunk -> 2 per thread
    auto cpB = [&](int c, int buf) {
        #pragma unroll
        for (int p = 0; p < 2; p++) {
            int idx = tid + p * 512;
            int r   = idx >> 2;
            int ch  = idx & 3;
            cp_async16(sb + SB(buf) + r * 80 + ch * 16,
                       g_Whi + (size_t)r * DD + c * 32 + ch * 8);
        }
        CP_COMMIT();
    };

    // ldmatrix lane addressing
    const int lrow = lane & 15;
    const int lkh  = lane >> 4;
    const uint32_t aAddr = sb + (uint32_t)((wr * 32 + lrow) * 80 + lkh * 16);
    const uint32_t bAddr = sb + (uint32_t)((wc * 64 + lrow) * 80 + lkh * 16);

    // ---- prologue ----
    float4 ar0, ar1;
    cpB(0, 0);
    ar0 = *reinterpret_cast<const float4*>(aptr);
    ar1 = *reinterpret_cast<const float4*>(aptr + 4);
    {
        uint4 hi, lo; cvt8h(ar0, ar1, hi, lo);
        *reinterpret_cast<uint4*>(smem + SA(0) + a_sts) = hi;
        *reinterpret_cast<uint4*>(smem + SA(0) + SA_LO_OFF + a_sts) = lo;
    }
    ar0 = *reinterpret_cast<const float4*>(aptr + 32);
    ar1 = *reinterpret_cast<const float4*>(aptr + 36);
    CP_WAIT(0);
    __syncthreads();

    #pragma unroll
    for (int c = 0; c < 8; c++) {
        const int buf = c & 1;
        // prefetch next chunk into the just-freed buffers
        if (c < 7) {
            cpB(c + 1, buf ^ 1);
            uint4 hi, lo; cvt8h(ar0, ar1, hi, lo);
            *reinterpret_cast<uint4*>(smem + SA(buf ^ 1) + a_sts) = hi;
            *reinterpret_cast<uint4*>(smem + SA(buf ^ 1) + SA_LO_OFF + a_sts) = lo;
        }
        if (c < 6) {
            ar0 = *reinterpret_cast<const float4*>(aptr + (c + 2) * 32);
            ar1 = *reinterpret_cast<const float4*>(aptr + (c + 2) * 32 + 4);
        }

        // ---- MMA chunk c: 2 products sharing B fragments ----
        const uint32_t aHi = aAddr + SA(buf);
        const uint32_t aLo = aHi + SA_LO_OFF;
        const uint32_t bB  = bAddr + SB(buf);
        #pragma unroll
        for (int ks = 0; ks < 2; ks++) {
            uint32_t ah[2][4], al[2][4];
            #pragma unroll
            for (int mt = 0; mt < 2; mt++) {
                ldsm4(ah[mt], aHi + mt * (16 * 80) + ks * 32);
                ldsm4(al[mt], aLo + mt * (16 * 80) + ks * 32);
            }
            #pragma unroll
            for (int ntp = 0; ntp < 4; ntp++) {
                uint32_t bf[4];
                ldsm4(bf, bB + ntp * (16 * 80) + ks * 32);
                #pragma unroll
                for (int mt = 0; mt < 2; mt++) {
                    mma16816(acc[mt][ntp * 2 + 0], ah[mt], bf[0], bf[2]);
                    mma16816(acc[mt][ntp * 2 + 1], ah[mt], bf[1], bf[3]);
                    mma16816(acc[mt][ntp * 2 + 0], al[mt], bf[0], bf[2]);
                    mma16816(acc[mt][ntp * 2 + 1], al[mt], bf[1], bf[3]);
                }
            }
        }
        if (c < 7) {
            CP_WAIT(0);
            __syncthreads();
        }
    }

    // ---- epilogue: tanh + score-weighted reduce over 256 e-columns ----
    const float* sbias = (const float*)(smem + SBIAS);
    const float* ssw   = (const float*)(smem + SSW);
    float* sred        = (float*)(smem + SRED);

    #pragma unroll
    for (int mt = 0; mt < 2; mt++) {
        #pragma unroll
        for (int h = 0; h < 2; h++) {
            float part = 0.0f;
            const int lrow_out = wr * 32 + mt * 16 + (lane >> 2) + h * 8;
            #pragma unroll
            for (int nt = 0; nt < 8; nt++) {
                const int col = wc * 64 + nt * 8 + (lane & 3) * 2;
                float2 bb = *reinterpret_cast<const float2*>(&sbias[col]);
                float2 ws = *reinterpret_cast<const float2*>(&ssw[col]);
                part = fmaf(tanh_fast(acc[mt][nt][h * 2 + 0] + bb.x), ws.x, part);
                part = fmaf(tanh_fast(acc[mt][nt][h * 2 + 1] + bb.y), ws.y, part);
            }
            part += __shfl_xor_sync(0xffffffffu, part, 1);
            part += __shfl_xor_sync(0xffffffffu, part, 2);
            if ((lane & 3) == 0) atomicAdd(&sred[lrow_out], part);
        }
    }
    __syncthreads();
    if (tid < 128) g_e[row0 + tid] = sred[tid];
}

// ---------------------------------------------------------------------------
// Kernel B: causal softmax-weighted prefix average (streaming hints added).
// ---------------------------------------------------------------------------
__global__ __launch_bounds__(256)
void attend_kernel(const float* __restrict__ H, float* __restrict__ C)
{
    __shared__ float se[TT];
    __shared__ float sw[TT];
    __shared__ float sinv[TT];

    const int n   = blockIdx.x;
    const int tid = threadIdx.x;

    for (int t = tid; t < TT; t += 256)
        se[t] = g_e[t * NN + n];
    __syncthreads();

    if (tid == 0) {
        float m = -INFINITY;
        #pragma unroll 8
        for (int t = 0; t < TT; t++) m = fmaxf(m, se[t]);
        float s = 0.0f;
        for (int t = 0; t < TT; t++) {
            float w = __expf(se[t] - m);
            s += w;
            sw[t]   = w;
            sinv[t] = __fdividef(1.0f, s);
        }
    }
    __syncthreads();

    const size_t stride = (size_t)NN * DD;
    const float* hp = H + (size_t)n * DD + tid;
    float*       cp = C + (size_t)n * DD + tid;

    float num = 0.0f;
    #pragma unroll 8
    for (int t = 0; t < TT; t++) {
        float h = __ldcs(hp + (size_t)t * stride);
        num = fmaf(sw[t], h, num);
        __stcs(cp + (size_t)t * stride, num * sinv[t]);
    }
}

// ---------------------------------------------------------------------------
extern "C" void kernel_launch(void* const* d_in, const int* in_sizes, int n_in,
                              void* d_out, int out_size)
{
    const float* H  = (const float*)d_in[0];
    const float* W  = (const float*)d_in[1];
    const float* b  = (const float*)d_in[2];
    const float* sv = (const float*)d_in[3];
    float* C = (float*)d_out;

    cudaFuncSetAttribute(gemm_score_hmma,
                         cudaFuncAttributeMaxDynamicSharedMemorySize, SMTOT);

    w_prep<<<16, 512>>>(W);
    gemm_score_hmma<<<M_ROWS / 128, 512, SMTOT>>>(H, b, sv);
    attend_kernel<<<NN, 256>>>(H, C);
}

// round 5
// speedup vs baseline: 3.2237x; 1.8105x over previous
#include <cuda_runtime.h>
#include <cuda_fp16.h>
#include <math.h>
#include <stdint.h>

#define TT 512
#define NN 1024
#define DD 256
#define M_ROWS (TT * NN)

__device__ float g_e[M_ROWS];
__device__ __align__(16) __half g_Whi[DD * DD];

// ---------------------------------------------------------------------------
// SMEM layout (bytes). 80B rows (32 halves + 16B pad): conflict-free ldmatrix.
//   A: buf*10240            (128 rows * 80)
//   B: 20480 + buf*20480    (256 rows * 80)
// ---------------------------------------------------------------------------
#define SA(buf)    ((buf) * 10240)
#define SB(buf)    (20480 + (buf) * 20480)
#define SBIAS      61440
#define SSW        62464
#define SRED       63488              // 512 floats: [wc][row]
#define SMTOT      65536

// ---------------------------------------------------------------------------
// PTX helpers (baseline ISA only -- toolchain targets sm_103, no tcgen05)
// ---------------------------------------------------------------------------
__device__ __forceinline__ uint32_t smem_u32(const void* p) {
    uint32_t a;
    asm("{ .reg .u64 t; cvta.to.shared.u64 t, %1; cvt.u32.u64 %0, t; }"
        : "=r"(a) : "l"(p));
    return a;
}
__device__ __forceinline__ void cp_async16(uint32_t dst, const void* src) {
    asm volatile("cp.async.cg.shared.global [%0], [%1], 16;"
                 :: "r"(dst), "l"(src) : "memory");
}
#define CP_COMMIT() asm volatile("cp.async.commit_group;" ::: "memory")
#define CP_WAIT(n)  asm volatile("cp.async.wait_group %0;" :: "n"(n) : "memory")

__device__ __forceinline__ void ldsm4(uint32_t* r, uint32_t addr) {
    asm volatile("ldmatrix.sync.aligned.m8n8.x4.shared.b16 {%0,%1,%2,%3}, [%4];"
                 : "=r"(r[0]), "=r"(r[1]), "=r"(r[2]), "=r"(r[3]) : "r"(addr));
}
__device__ __forceinline__ void mma16816(float* c, const uint32_t* a,
                                         uint32_t b0, uint32_t b1) {
    asm volatile(
        "mma.sync.aligned.m16n8k16.row.col.f32.f16.f16.f32 "
        "{%0,%1,%2,%3}, {%4,%5,%6,%7}, {%8,%9}, {%0,%1,%2,%3};"
        : "+f"(c[0]), "+f"(c[1]), "+f"(c[2]), "+f"(c[3])
        : "r"(a[0]), "r"(a[1]), "r"(a[2]), "r"(a[3]), "r"(b0), "r"(b1));
}

// fp32 x8 -> fp16 x8 (hi only, 4 pack instructions)
__device__ __forceinline__ uint4 cvt8hi(const float4& u, const float4& v) {
    __half2 h0 = __floats2half2_rn(u.x, u.y);
    __half2 h1 = __floats2half2_rn(u.z, u.w);
    __half2 h2 = __floats2half2_rn(v.x, v.y);
    __half2 h3 = __floats2half2_rn(v.z, v.w);
    uint4 hi;
    hi.x = *(uint32_t*)&h0; hi.y = *(uint32_t*)&h1;
    hi.z = *(uint32_t*)&h2; hi.w = *(uint32_t*)&h3;
    return hi;
}

// tanh via MUFU (EX2 + RCP), ~6 ops, rel err ~1e-6. Handles inf correctly.
__device__ __forceinline__ float tanh_mufu(float z) {
    float u = __expf(2.0f * z);                 // MUFU.EX2 path
    return 1.0f - __fdividef(2.0f, u + 1.0f);   // MUFU.RCP path
}

// ---------------------------------------------------------------------------
// Prep: W (256x256 fp32, [e][k]) -> fp16 once.
// ---------------------------------------------------------------------------
__global__ void w_prep(const float* __restrict__ W) {
    int i = blockIdx.x * blockDim.x + threadIdx.x;      // 8192 thr * 8 elems
    const float4* p = reinterpret_cast<const float4*>(W) + i * 2;
    reinterpret_cast<uint4*>(g_Whi)[i] = cvt8hi(p[0], p[1]);
}

// ---------------------------------------------------------------------------
// Kernel A: single-product fp16 HMMA GEMM + MUFU tanh + score reduce -> g_e
// grid = 4096 (M/128), 512 threads (16 warps: 4 row-groups x 4 col-groups).
// ---------------------------------------------------------------------------
__global__ __launch_bounds__(512, 1)
void gemm_score_hmma(const float* __restrict__ H,
                     const float* __restrict__ bias,
                     const float* __restrict__ swt)
{
    extern __shared__ char smem[];
    const uint32_t sb = smem_u32(smem);
    const int tid  = threadIdx.x;
    const int lane = tid & 31;
    const int warp = tid >> 5;
    const int wr   = warp >> 2;       // 0..3: rows 32*wr
    const int wc   = warp & 3;        // 0..3: cols 64*wc
    const int row0 = blockIdx.x * 128;

    if (tid < 256) {
        ((float*)(smem + SBIAS))[tid] = bias[tid];
        ((float*)(smem + SSW))[tid]   = swt[tid];
    }

    // A loader mapping: each thread owns 8 k of one row
    const int arow  = tid >> 2;
    const int akseg = tid & 3;
    const float* aptr = H + (size_t)(row0 + arow) * DD + akseg * 8;
    const uint32_t a_sts = (uint32_t)(arow * 80 + akseg * 16);

    float acc[2][8][4];
    #pragma unroll
    for (int m = 0; m < 2; m++)
        #pragma unroll
        for (int n = 0; n < 8; n++)
            #pragma unroll
            for (int e = 0; e < 4; e++) acc[m][n][e] = 0.0f;

    // B cp.async: 1024 x 16B per chunk -> 2 per thread
    auto cpB = [&](int c, int buf) {
        #pragma unroll
        for (int p = 0; p < 2; p++) {
            int idx = tid + p * 512;
            int r   = idx >> 2;
            int ch  = idx & 3;
            cp_async16(sb + SB(buf) + r * 80 + ch * 16,
                       g_Whi + (size_t)r * DD + c * 32 + ch * 8);
        }
        CP_COMMIT();
    };

    // ldmatrix lane addressing
    const int lrow = lane & 15;
    const int lkh  = lane >> 4;
    const uint32_t aAddr = sb + (uint32_t)((wr * 32 + lrow) * 80 + lkh * 16);
    const uint32_t bAddr = sb + (uint32_t)((wc * 64 + lrow) * 80 + lkh * 16);

    // ---- prologue ----
    float4 ar0, ar1;
    cpB(0, 0);
    ar0 = *reinterpret_cast<const float4*>(aptr);
    ar1 = *reinterpret_cast<const float4*>(aptr + 4);
    *reinterpret_cast<uint4*>(smem + SA(0) + a_sts) = cvt8hi(ar0, ar1);
    ar0 = *reinterpret_cast<const float4*>(aptr + 32);
    ar1 = *reinterpret_cast<const float4*>(aptr + 36);
    CP_WAIT(0);
    __syncthreads();

    #pragma unroll
    for (int c = 0; c < 8; c++) {
        const int buf = c & 1;
        if (c < 7) {
            cpB(c + 1, buf ^ 1);
            *reinterpret_cast<uint4*>(smem + SA(buf ^ 1) + a_sts) =
                cvt8hi(ar0, ar1);
        }
        if (c < 6) {
            ar0 = *reinterpret_cast<const float4*>(aptr + (c + 2) * 32);
            ar1 = *reinterpret_cast<const float4*>(aptr + (c + 2) * 32 + 4);
        }

        // ---- MMA chunk c: single fp16 product ----
        const uint32_t aA = aAddr + SA(buf);
        const uint32_t bB = bAddr + SB(buf);
        #pragma unroll
        for (int ks = 0; ks < 2; ks++) {
            uint32_t ah[2][4];
            ldsm4(ah[0], aA + ks * 32);
            ldsm4(ah[1], aA + 16 * 80 + ks * 32);
            #pragma unroll
            for (int ntp = 0; ntp < 4; ntp++) {
                uint32_t bf[4];
                ldsm4(bf, bB + ntp * (16 * 80) + ks * 32);
                #pragma unroll
                for (int mt = 0; mt < 2; mt++) {
                    mma16816(acc[mt][ntp * 2 + 0], ah[mt], bf[0], bf[2]);
                    mma16816(acc[mt][ntp * 2 + 1], ah[mt], bf[1], bf[3]);
                }
            }
        }
        if (c < 7) {
            CP_WAIT(0);
            __syncthreads();
        }
    }

    // ---- epilogue: MUFU tanh + score reduce (atomic-free) ----
    const float* sbias = (const float*)(smem + SBIAS);
    const float* ssw   = (const float*)(smem + SSW);
    float* sred        = (float*)(smem + SRED);

    #pragma unroll
    for (int mt = 0; mt < 2; mt++) {
        #pragma unroll
        for (int h = 0; h < 2; h++) {
            float part = 0.0f;
            const int lrow_out = wr * 32 + mt * 16 + (lane >> 2) + h * 8;
            #pragma unroll
            for (int nt = 0; nt < 8; nt++) {
                const int col = wc * 64 + nt * 8 + (lane & 3) * 2;
                float2 bb = *reinterpret_cast<const float2*>(&sbias[col]);
                float2 ws = *reinterpret_cast<const float2*>(&ssw[col]);
                part = fmaf(tanh_mufu(acc[mt][nt][h * 2 + 0] + bb.x), ws.x, part);
                part = fmaf(tanh_mufu(acc[mt][nt][h * 2 + 1] + bb.y), ws.y, part);
            }
            part += __shfl_xor_sync(0xffffffffu, part, 1);
            part += __shfl_xor_sync(0xffffffffu, part, 2);
            if ((lane & 3) == 0) sred[wc * 128 + lrow_out] = part;
        }
    }
    __syncthreads();
    if (tid < 128)
        g_e[row0 + tid] = (sred[tid] + sred[128 + tid]) +
                          (sred[256 + tid] + sred[384 + tid]);
}

// ---------------------------------------------------------------------------
// Kernel B: causal softmax-weighted prefix average (streaming hints).
// ---------------------------------------------------------------------------
__global__ __launch_bounds__(256)
void attend_kernel(const float* __restrict__ H, float* __restrict__ C)
{
    __shared__ float se[TT];
    __shared__ float sw[TT];
    __shared__ float sinv[TT];

    const int n   = blockIdx.x;
    const int tid = threadIdx.x;

    for (int t = tid; t < TT; t += 256)
        se[t] = g_e[t * NN + n];
    __syncthreads();

    if (tid == 0) {
        float m = -INFINITY;
        #pragma unroll 8
        for (int t = 0; t < TT; t++) m = fmaxf(m, se[t]);
        float s = 0.0f;
        for (int t = 0; t < TT; t++) {
            float w = __expf(se[t] - m);
            s += w;
            sw[t]   = w;
            sinv[t] = __fdividef(1.0f, s);
        }
    }
    __syncthreads();

    const size_t stride = (size_t)NN * DD;
    const float* hp = H + (size_t)n * DD + tid;
    float*       cp = C + (size_t)n * DD + tid;

    float num = 0.0f;
    #pragma unroll 8
    for (int t = 0; t < TT; t++) {
        float h = __ldcs(hp + (size_t)t * stride);
        num = fmaf(sw[t], h, num);
        __stcs(cp + (size_t)t * stride, num * sinv[t]);
    }
}

// ---------------------------------------------------------------------------
extern "C" void kernel_launch(void* const* d_in, const int* in_sizes, int n_in,
                              void* d_out, int out_size)
{
    const float* H  = (const float*)d_in[0];
    const float* W  = (const float*)d_in[1];
    const float* b  = (const float*)d_in[2];
    const float* sv = (const float*)d_in[3];
    float* C = (float*)d_out;

    cudaFuncSetAttribute(gemm_score_hmma,
                         cudaFuncAttributeMaxDynamicSharedMemorySize, SMTOT);

    w_prep<<<16, 512>>>(W);
    gemm_score_hmma<<<M_ROWS / 128, 512, SMTOT>>>(H, b, sv);
    attend_kernel<<<NN, 256>>>(H, C);
}